// round 14
// baseline (speedup 1.0000x reference)
#include <cuda_runtime.h>
#include <cuda_bf16.h>
#include <cstdint>
#include <cstddef>

#define DD    256
#define KK    1024
#define NVEC  32768
#define QSIZE (32*256*32*32)

#define MROWS 64
#define KCH   64
#define NCH   16
#define BROW  512          // bytes per tile row (A and B, linear, swizzled content)
#define XSTR  260          // fp32 rescore tile stride
#define CAP   20
#define EPS   4e-3f        // validated: zero flips

__device__ float g_enorm[KK];
__device__ __align__(16) __nv_bfloat16 g_eb[KK * DD];   // PRE-SWIZZLED rows

// ---- smem layout (bytes); 74528 -> 3 CTAs/SM ----
#define A_OFF    0
#define A_B      (MROWS * BROW)              // 32768
#define B_OFF    A_B
#define B_B      (KCH * BROW)                // 32768
#define EN_OFF   65536                        // 512 (dead after mainloop)
#define MV_OFF   66048                        // 256 (dead after mainloop)
// xrs overlays [0, 66560) after mainloop (A,B,EN,MV,pad)
#define CT_OFF   66560                        // 64 i32
#define XN_OFF   66816                        // 64 f32
#define IDX_OFF  67072                        // 64 i32
#define MB_OFF   67328                        // mbarrier (32 B slot)
#define CAND_OFF 67360                        // 64*CAP i32 = 5120
#define BS_OFF   72480                        // 256 f32
#define BK_OFF   73504                        // 256 i32
#define SMEM_GEMM 74528

__device__ __forceinline__ unsigned fenc(float f) {
    unsigned u = __float_as_uint(f);
    return (u & 0x80000000u) ? ~u : (u | 0x80000000u);
}
__device__ __forceinline__ float fdec(unsigned e) {
    return __uint_as_float((e & 0x80000000u) ? (e ^ 0x80000000u) : ~e);
}
__device__ __forceinline__ void bulk_cp(uint32_t dst, const void* src,
                                        uint32_t bytes, uint32_t mbar) {
    asm volatile(
        "cp.async.bulk.shared::cluster.global.mbarrier::complete_tx::bytes "
        "[%0], [%1], %2, [%3];"
        :: "r"(dst), "l"(src), "r"(bytes), "r"(mbar) : "memory");
}
__device__ __forceinline__ void mbar_wait(uint32_t mbar, unsigned parity) {
    asm volatile(
        "{\n\t.reg .pred P1;\n\t"
        "WL_%=:\n\t"
        "mbarrier.try_wait.parity.acquire.cta.shared::cta.b64 P1, [%0], %1, 0x989680;\n\t"
        "@P1 bra.uni WD_%=;\n\t"
        "bra.uni WL_%=;\n\t"
        "WD_%=:\n\t}"
        :: "r"(mbar), "r"(parity) : "memory");
}
__device__ __forceinline__ void ldsm4(uint32_t& r0, uint32_t& r1,
                                      uint32_t& r2, uint32_t& r3, uint32_t a) {
    asm volatile("ldmatrix.sync.aligned.m8n8.x4.shared.b16 {%0,%1,%2,%3}, [%4];"
                 : "=r"(r0), "=r"(r1), "=r"(r2), "=r"(r3) : "r"(a));
}
__device__ __forceinline__ void mma_bf16(float& c0, float& c1, float& c2, float& c3,
                                         uint32_t a0, uint32_t a1, uint32_t a2, uint32_t a3,
                                         uint32_t b0, uint32_t b1) {
    asm volatile("mma.sync.aligned.m16n8k16.row.col.f32.bf16.bf16.f32 "
                 "{%0,%1,%2,%3},{%4,%5,%6,%7},{%8,%9},{%0,%1,%2,%3};"
                 : "+f"(c0), "+f"(c1), "+f"(c2), "+f"(c3)
                 : "r"(a0), "r"(a1), "r"(a2), "r"(a3), "r"(b0), "r"(b1));
}

// ---------------------------------------------------------------------------
// prep: enorm + PRE-SWIZZLED bf16 codebook (chunk-XOR within 512B rows).
// ---------------------------------------------------------------------------
__global__ void __launch_bounds__(256)
prep_kernel(const float* __restrict__ codebook,
            float* __restrict__ d_out, int out_size) {
    int t = blockIdx.x * blockDim.x + threadIdx.x;
    int k = t >> 5, lane = t & 31;
    if (k < KK) {
        const float* p = codebook + (size_t)k * DD;
        const int sw = (k & 7) << 3;
        float s = 0.0f;
        #pragma unroll
        for (int j = 0; j < DD / 32; j++) {
            int d = lane + j * 32;
            float v = p[d];
            g_eb[(size_t)k * DD + (d ^ sw)] = __float2bfloat16(v);
            s = __fadd_rn(s, __fmul_rn(v, v));
        }
        #pragma unroll
        for (int o = 16; o; o >>= 1) s += __shfl_down_sync(0xffffffffu, s, o);
        if (lane == 0) g_enorm[k] = s;
    }
    if (t == 0 && out_size > QSIZE) d_out[QSIZE] = 0.0f;
}

// ---------------------------------------------------------------------------
// Fused GEMM + select + exact rescore + gather/output + loss.
// 64 rows x 64-code chunks; 3 CTAs/SM target.
// ---------------------------------------------------------------------------
__global__ void __launch_bounds__(256, 3)
gemm_select_kernel(const float* __restrict__ latent,
                   const float* __restrict__ codebook,
                   float* __restrict__ d_out, int out_size) {
    extern __shared__ __align__(1024) char sm[];
    const uint32_t smb = (uint32_t)__cvta_generic_to_shared(sm);
    float*    enorm_s = (float*)(sm + EN_OFF);
    unsigned* minval  = (unsigned*)(sm + MV_OFF);
    int*      cnt     = (int*)(sm + CT_OFF);
    float*    xn_s    = (float*)(sm + XN_OFF);
    int*      idxs    = (int*)(sm + IDX_OFF);
    int*      cand    = (int*)(sm + CAND_OFF);
    float*    bS      = (float*)(sm + BS_OFF);
    int*      bK      = (int*)(sm + BK_OFF);
    const uint32_t mbar = smb + MB_OFF;

    const int tid  = threadIdx.x;
    const int lane = tid & 31, wid = tid >> 5;
    const int wm   = wid >> 2, wn = wid & 3;     // 2 x 4 warp grid
    const int g    = lane >> 2, tq = lane & 3;
    const int n0   = blockIdx.x * MROWS;
    const int b    = n0 >> 10;
    const int hw0  = n0 & 1023;

    if (tid == 0)
        asm volatile("mbarrier.init.shared.b64 [%0], 1;" :: "r"(mbar) : "memory");
    if (tid < MROWS) { minval[tid] = 0xFFFFFFFFu; cnt[tid] = 0; }

    // Stage A from latent: coalesced over hw; swizzled linear 512B rows.
    {
        const int hw = tid & 63, dg = tid >> 6;
        const float* latb = latent + ((size_t)b * DD + dg * 64) * 1024 + hw0 + hw;
        uint32_t* arow = (uint32_t*)(sm + A_OFF + hw * BROW);
        const int hx = hw & 7;
        #pragma unroll
        for (int j = 0; j < 16; j++) {
            float v0 = latb[(size_t)(j * 4 + 0) * 1024];
            float v1 = latb[(size_t)(j * 4 + 1) * 1024];
            float v2 = latb[(size_t)(j * 4 + 2) * 1024];
            float v3 = latb[(size_t)(j * 4 + 3) * 1024];
            uint32_t p0 = ((uint32_t)__bfloat16_as_ushort(__float2bfloat16(v1)) << 16)
                        |  (uint32_t)__bfloat16_as_ushort(__float2bfloat16(v0));
            uint32_t p1 = ((uint32_t)__bfloat16_as_ushort(__float2bfloat16(v3)) << 16)
                        |  (uint32_t)__bfloat16_as_ushort(__float2bfloat16(v2));
            int idx = (((dg * 8 + (j >> 1)) ^ hx) << 2) + (j & 1) * 2;
            arow[idx]     = p0;
            arow[idx + 1] = p1;
        }
    }

    // ldsm address parameters (swizzled linear rows)
    uint32_t aBase[2], arx[2];
    const uint32_t ah = lane >> 4;               // 0/1: 16B half of 32B k-step
    #pragma unroll
    for (int mi = 0; mi < 2; mi++) {
        uint32_t row = wm * 32 + mi * 16 + (lane & 15);
        aBase[mi] = smb + A_OFF + row * BROW;
        arx[mi] = row & 7;
    }
    uint32_t bBase, brx;
    const uint32_t hs = (lane >> 3) & 1;
    {
        uint32_t r = wn * 16 + (lane & 7) + ((lane >> 4) & 1) * 8;
        bBase = smb + B_OFF + r * BROW;
        brx = r & 7;
    }

    for (int c = 0; c < NCH; c++) {
        const int kb = c * KCH;
        __syncthreads();                         // prev B consumed; init visible
        if (tid == 0) {
            asm volatile("mbarrier.arrive.expect_tx.shared.b64 _, [%0], %1;"
                         :: "r"(mbar), "r"((uint32_t)B_B) : "memory");
            bulk_cp(smb + B_OFF, g_eb + (size_t)kb * DD, B_B, mbar);
        }
        if (tid < KCH) enorm_s[tid] = g_enorm[kb + tid];
        mbar_wait(mbar, c & 1);
        __syncthreads();

        float acc[2][2][4];
        #pragma unroll
        for (int mi = 0; mi < 2; mi++)
            #pragma unroll
            for (int ni = 0; ni < 2; ni++)
                #pragma unroll
                for (int jj = 0; jj < 4; jj++) acc[mi][ni][jj] = 0.0f;

        #pragma unroll
        for (int ds = 0; ds < 16; ds++) {
            uint32_t a[2][4], bfr[2][2];
            #pragma unroll
            for (int mi = 0; mi < 2; mi++) {
                uint32_t aaddr = aBase[mi] + ((((uint32_t)(ds << 1) | ah) ^ arx[mi]) << 4);
                ldsm4(a[mi][0], a[mi][1], a[mi][2], a[mi][3], aaddr);
            }
            {
                uint32_t baddr = bBase + ((((uint32_t)(ds << 1) | hs) ^ brx) << 4);
                ldsm4(bfr[0][0], bfr[0][1], bfr[1][0], bfr[1][1], baddr);
            }
            #pragma unroll
            for (int mi = 0; mi < 2; mi++)
                #pragma unroll
                for (int ni = 0; ni < 2; ni++)
                    mma_bf16(acc[mi][ni][0], acc[mi][ni][1], acc[mi][ni][2], acc[mi][ni][3],
                             a[mi][0], a[mi][1], a[mi][2], a[mi][3],
                             bfr[ni][0], bfr[ni][1]);
        }

        // scores in place; per-row running min
        #pragma unroll
        for (int mi = 0; mi < 2; mi++) {
            float m0 = 3.4e38f, m1 = 3.4e38f;
            #pragma unroll
            for (int ni = 0; ni < 2; ni++) {
                int cl = wn * 16 + ni * 8 + 2 * tq;
                float e0 = enorm_s[cl], e1 = enorm_s[cl + 1];
                acc[mi][ni][0] = e0 - 2.0f * acc[mi][ni][0];
                acc[mi][ni][1] = e1 - 2.0f * acc[mi][ni][1];
                acc[mi][ni][2] = e0 - 2.0f * acc[mi][ni][2];
                acc[mi][ni][3] = e1 - 2.0f * acc[mi][ni][3];
                m0 = fminf(m0, fminf(acc[mi][ni][0], acc[mi][ni][1]));
                m1 = fminf(m1, fminf(acc[mi][ni][2], acc[mi][ni][3]));
            }
            m0 = fminf(m0, __shfl_xor_sync(0xffffffffu, m0, 1));
            m0 = fminf(m0, __shfl_xor_sync(0xffffffffu, m0, 2));
            m1 = fminf(m1, __shfl_xor_sync(0xffffffffu, m1, 1));
            m1 = fminf(m1, __shfl_xor_sync(0xffffffffu, m1, 2));
            if (tq == 0) {
                atomicMin(&minval[wm * 32 + mi * 16 + g],     fenc(m0));
                atomicMin(&minval[wm * 32 + mi * 16 + g + 8], fenc(m1));
            }
        }
        __syncthreads();

        #pragma unroll
        for (int mi = 0; mi < 2; mi++) {
            int rl0 = wm * 32 + mi * 16 + g, rl1 = rl0 + 8;
            float t0 = fdec(minval[rl0]) + EPS;
            float t1 = fdec(minval[rl1]) + EPS;
            #pragma unroll
            for (int ni = 0; ni < 2; ni++) {
                int k0 = kb + wn * 16 + ni * 8 + 2 * tq;
                if (acc[mi][ni][0] <= t0) { int p = atomicAdd(&cnt[rl0], 1); if (p < CAP) cand[rl0 * CAP + p] = k0; }
                if (acc[mi][ni][1] <= t0) { int p = atomicAdd(&cnt[rl0], 1); if (p < CAP) cand[rl0 * CAP + p] = k0 + 1; }
                if (acc[mi][ni][2] <= t1) { int p = atomicAdd(&cnt[rl1], 1); if (p < CAP) cand[rl1 * CAP + p] = k0; }
                if (acc[mi][ni][3] <= t1) { int p = atomicAdd(&cnt[rl1], 1); if (p < CAP) cand[rl1 * CAP + p] = k0 + 1; }
            }
        }
    }
    __syncthreads();

    // ---- exact rescore: reload fp32 x over dead A/B/EN/MV area ----
    float* xrs = (float*)sm;                     // [64][XSTR] = 66560 B
    {
        const int hw = tid & 63, dg = tid >> 6;
        const float* latb = latent + ((size_t)b * DD + dg * 64) * 1024 + hw0 + hw;
        float* xrow = xrs + hw * XSTR + dg * 64;
        #pragma unroll 8
        for (int j = 0; j < 64; j++)
            xrow[j] = latb[(size_t)j * 1024];
    }
    __syncthreads();
    if (tid < MROWS) {
        const float4* xr = (const float4*)(xrs + tid * XSTR);
        float sum = 0.0f;
        #pragma unroll 8
        for (int i = 0; i < DD / 4; i++) {
            float4 v = xr[i];
            sum = __fadd_rn(sum, __fmul_rn(v.x, v.x));
            sum = __fadd_rn(sum, __fmul_rn(v.y, v.y));
            sum = __fadd_rn(sum, __fmul_rn(v.z, v.z));
            sum = __fadd_rn(sum, __fmul_rn(v.w, v.w));
        }
        xn_s[tid] = sum;
    }
    __syncthreads();
    {
        int r = tid >> 2, c0 = tid & 3;
        int cnr = cnt[r];
        float xn = xn_s[r];
        const float4* xp = (const float4*)(xrs + r * XSTR);
        float bs = 3.4e38f; int bi = 0x7fffffff;
        if (cnr <= CAP) {
            for (int cc = c0; cc < cnr; cc += 4) {
                int k = cand[r * CAP + cc];
                const float4* ep = (const float4*)(codebook + (size_t)k * DD);
                float a = 0.0f;
                #pragma unroll 8
                for (int i = 0; i < DD / 4; i++) {
                    float4 xv = xp[i], ev = ep[i];
                    a = fmaf(xv.x, ev.x, a); a = fmaf(xv.y, ev.y, a);
                    a = fmaf(xv.z, ev.z, a); a = fmaf(xv.w, ev.w, a);
                }
                float sc = __fsub_rn(__fadd_rn(xn, g_enorm[k]), __fmul_rn(2.0f, a));
                if (sc < bs || (sc == bs && k < bi)) { bs = sc; bi = k; }
            }
        } else {
            for (int k = c0; k < KK; k += 4) {   // backstop: exact scan
                const float4* ep = (const float4*)(codebook + (size_t)k * DD);
                float a = 0.0f;
                #pragma unroll 8
                for (int i = 0; i < DD / 4; i++) {
                    float4 xv = xp[i], ev = ep[i];
                    a = fmaf(xv.x, ev.x, a); a = fmaf(xv.y, ev.y, a);
                    a = fmaf(xv.z, ev.z, a); a = fmaf(xv.w, ev.w, a);
                }
                float sc = __fsub_rn(__fadd_rn(xn, g_enorm[k]), __fmul_rn(2.0f, a));
                if (sc < bs || (sc == bs && k < bi)) { bs = sc; bi = k; }
            }
        }
        bS[c0 * 64 + r] = bs;
        bK[c0 * 64 + r] = bi;
    }
    __syncthreads();
    if (tid < MROWS) {
        float bs = bS[tid]; int bi = bK[tid];
        #pragma unroll
        for (int cc = 1; cc < 4; cc++) {
            float s = bS[cc * 64 + tid]; int k = bK[cc * 64 + tid];
            if (s < bs || (s == bs && k < bi)) { bs = s; bi = k; }
        }
        idxs[tid] = bi;
    }
    __syncthreads();

    // ---- fused gather + output + loss ----
    {
        const int hw = tid & 63, dg = tid >> 6;
        const int kidx = idxs[hw];
        const float4* qrow  = (const float4*)(codebook + (size_t)kidx * DD + dg * 64);
        const float4* xrow4 = (const float4*)(xrs + hw * XSTR + dg * 64);
        float* outb = d_out + ((size_t)b * DD + dg * 64) * 1024 + hw0 + hw;
        float lsum = 0.0f;
        #pragma unroll
        for (int jq = 0; jq < 16; jq++) {
            float4 xv = xrow4[jq];
            float4 qv = __ldg(qrow + jq);
            float d0 = __fsub_rn(qv.x, xv.x);
            float d1 = __fsub_rn(qv.y, xv.y);
            float d2 = __fsub_rn(qv.z, xv.z);
            float d3 = __fsub_rn(qv.w, xv.w);
            outb[(size_t)(jq * 4 + 0) * 1024] = __fadd_rn(xv.x, d0);
            outb[(size_t)(jq * 4 + 1) * 1024] = __fadd_rn(xv.y, d1);
            outb[(size_t)(jq * 4 + 2) * 1024] = __fadd_rn(xv.z, d2);
            outb[(size_t)(jq * 4 + 3) * 1024] = __fadd_rn(xv.w, d3);
            lsum += d0 * d0 + d1 * d1 + d2 * d2 + d3 * d3;
        }
        float* red = (float*)cand;
        red[tid] = lsum;
        __syncthreads();
        #pragma unroll
        for (int s = 128; s > 0; s >>= 1) {
            if (tid < s) red[tid] += red[tid + s];
            __syncthreads();
        }
        if (tid == 0 && out_size > QSIZE)
            atomicAdd(d_out + QSIZE, 1.25f * red[0] * (1.0f / (float)QSIZE));
    }
}

extern "C" void kernel_launch(void* const* d_in, const int* in_sizes, int n_in,
                              void* d_out, int out_size) {
    const float* latent   = (const float*)d_in[0];
    const float* codebook = (const float*)d_in[1];
    float* out = (float*)d_out;

    cudaFuncSetAttribute(gemm_select_kernel,
                         cudaFuncAttributeMaxDynamicSharedMemorySize, SMEM_GEMM);

    prep_kernel<<<KK * 32 / 256, 256>>>(codebook, out, out_size);
    gemm_select_kernel<<<NVEC / MROWS, 256, SMEM_GEMM>>>(latent, codebook, out, out_size);
}

// round 15
// speedup vs baseline: 4.2039x; 4.2039x over previous
#include <cuda_runtime.h>
#include <cuda_bf16.h>
#include <cstdint>
#include <cstddef>

#define DD    256
#define KK    1024
#define NVEC  32768
#define QSIZE (32*256*32*32)

#define MROWS 64
#define KH    64           // codes per half-buffer
#define NH    16           // halves
#define ASTR  264          // A: bf16 elements per row (padded, R13-validated)
#define BROW  512          // B: bytes per code row (linear, swizzled content)
#define XSTR  260          // fp32 rescore tile stride
#define CAP   28
#define EPS   4e-3f        // validated: zero flips

__device__ float g_enorm[KK];
__device__ __align__(16) __nv_bfloat16 g_eb[KK * DD];   // PRE-SWIZZLED rows

// ---- smem layout (bytes); ~110 KB -> 2 CTAs/SM ----
#define A_OFF    0
#define A_B      (MROWS * ASTR * 2)          // 33792
#define B0_OFF   A_B
#define B1_OFF   (A_B + KH * BROW)           // +32768
#define B_HALF   (KH * BROW)                 // 32768
#define CTRL     (A_B + 2 * B_HALF)          // 99328
#define MV_OFF   (CTRL)                      // 64 u32
#define CT_OFF   (MV_OFF + 256)              // 64 i32
#define XN_OFF   (CT_OFF + 256)              // 64 f32
#define IDX_OFF  (XN_OFF + 256)              // 64 i32
#define MB_OFF   (IDX_OFF + 256)             // 2 mbarriers (32 B)
#define CAND_OFF (MB_OFF + 32)               // 64*CAP i32 = 7168
#define BS_OFF   (CAND_OFF + 64*CAP*4)       // 256 f32
#define BK_OFF   (BS_OFF + 1024)             // 256 i32
#define SMEM_GEMM (BK_OFF + 1024)            // 109632 B

__device__ __forceinline__ unsigned fenc(float f) {
    unsigned u = __float_as_uint(f);
    return (u & 0x80000000u) ? ~u : (u | 0x80000000u);
}
__device__ __forceinline__ float fdec(unsigned e) {
    return __uint_as_float((e & 0x80000000u) ? (e ^ 0x80000000u) : ~e);
}
__device__ __forceinline__ void bulk_cp(uint32_t dst, const void* src,
                                        uint32_t bytes, uint32_t mbar) {
    asm volatile(
        "cp.async.bulk.shared::cluster.global.mbarrier::complete_tx::bytes "
        "[%0], [%1], %2, [%3];"
        :: "r"(dst), "l"(src), "r"(bytes), "r"(mbar) : "memory");
}
__device__ __forceinline__ void mbar_wait(uint32_t mbar, unsigned parity) {
    asm volatile(
        "{\n\t.reg .pred P1;\n\t"
        "WL_%=:\n\t"
        "mbarrier.try_wait.parity.acquire.cta.shared::cta.b64 P1, [%0], %1, 0x989680;\n\t"
        "@P1 bra.uni WD_%=;\n\t"
        "bra.uni WL_%=;\n\t"
        "WD_%=:\n\t}"
        :: "r"(mbar), "r"(parity) : "memory");
}
__device__ __forceinline__ void ldsm4(uint32_t& r0, uint32_t& r1,
                                      uint32_t& r2, uint32_t& r3, uint32_t a) {
    asm volatile("ldmatrix.sync.aligned.m8n8.x4.shared.b16 {%0,%1,%2,%3}, [%4];"
                 : "=r"(r0), "=r"(r1), "=r"(r2), "=r"(r3) : "r"(a));
}
__device__ __forceinline__ void ldsm2(uint32_t& r0, uint32_t& r1, uint32_t a) {
    asm volatile("ldmatrix.sync.aligned.m8n8.x2.shared.b16 {%0,%1}, [%2];"
                 : "=r"(r0), "=r"(r1) : "r"(a));
}
__device__ __forceinline__ void mma_bf16(float& c0, float& c1, float& c2, float& c3,
                                         uint32_t a0, uint32_t a1, uint32_t a2, uint32_t a3,
                                         uint32_t b0, uint32_t b1) {
    asm volatile("mma.sync.aligned.m16n8k16.row.col.f32.bf16.bf16.f32 "
                 "{%0,%1,%2,%3},{%4,%5,%6,%7},{%8,%9},{%0,%1,%2,%3};"
                 : "+f"(c0), "+f"(c1), "+f"(c2), "+f"(c3)
                 : "r"(a0), "r"(a1), "r"(a2), "r"(a3), "r"(b0), "r"(b1));
}

// ---------------------------------------------------------------------------
// prep: enorm + PRE-SWIZZLED bf16 codebook (chunk-XOR within 512B rows).
// ---------------------------------------------------------------------------
__global__ void __launch_bounds__(256)
prep_kernel(const float* __restrict__ codebook,
            float* __restrict__ d_out, int out_size) {
    int t = blockIdx.x * blockDim.x + threadIdx.x;
    int k = t >> 5, lane = t & 31;
    if (k < KK) {
        const float* p = codebook + (size_t)k * DD;
        const int sw = (k & 7) << 3;
        float s = 0.0f;
        #pragma unroll
        for (int j = 0; j < DD / 32; j++) {
            int d = lane + j * 32;
            float v = p[d];
            g_eb[(size_t)k * DD + (d ^ sw)] = __float2bfloat16(v);
            s = __fadd_rn(s, __fmul_rn(v, v));
        }
        #pragma unroll
        for (int o = 16; o; o >>= 1) s += __shfl_down_sync(0xffffffffu, s, o);
        if (lane == 0) g_enorm[k] = s;
    }
    if (t == 0 && out_size > QSIZE) d_out[QSIZE] = 0.0f;
}

// ---------------------------------------------------------------------------
// Fused GEMM (double-buffered 64-code halves via bulk TMA) + select +
// exact rescore + gather/output + loss. 2 CTAs/SM, no register cap.
// ---------------------------------------------------------------------------
__global__ void __launch_bounds__(256, 2)
gemm_select_kernel(const float* __restrict__ latent,
                   const float* __restrict__ codebook,
                   float* __restrict__ d_out, int out_size) {
    extern __shared__ __align__(1024) char sm[];
    const uint32_t smb = (uint32_t)__cvta_generic_to_shared(sm);
    __nv_bfloat16* As = (__nv_bfloat16*)(sm + A_OFF);
    unsigned* minval  = (unsigned*)(sm + MV_OFF);
    int*      cnt     = (int*)(sm + CT_OFF);
    float*    xn_s    = (float*)(sm + XN_OFF);
    int*      idxs    = (int*)(sm + IDX_OFF);
    int*      cand    = (int*)(sm + CAND_OFF);
    float*    bS      = (float*)(sm + BS_OFF);
    int*      bK      = (int*)(sm + BK_OFF);

    const int tid  = threadIdx.x;
    const int lane = tid & 31, wid = tid >> 5;
    const int wm   = wid >> 2, wn = wid & 3;     // 2 x 4 warp grid
    const int g    = lane >> 2, tq = lane & 3;
    const int n0   = blockIdx.x * MROWS;
    const int b    = n0 >> 10;
    const int hw0  = n0 & 1023;

    if (tid == 0) {
        asm volatile("mbarrier.init.shared.b64 [%0], 1;" :: "r"(smb + MB_OFF) : "memory");
        asm volatile("mbarrier.init.shared.b64 [%0], 1;" :: "r"(smb + MB_OFF + 16) : "memory");
    }
    if (tid < MROWS) { minval[tid] = 0xFFFFFFFFu; cnt[tid] = 0; }

    // Stage A from latent (R13-validated padded layout), coalesced over hw.
    {
        const int hw = tid & 63, dg = tid >> 6;
        const float* latb = latent + ((size_t)b * DD + dg * 64) * 1024 + hw0 + hw;
        uint32_t* arow = (uint32_t*)(As + hw * ASTR + dg * 64);
        #pragma unroll
        for (int j = 0; j < 16; j++) {
            float v0 = latb[(size_t)(j * 4 + 0) * 1024];
            float v1 = latb[(size_t)(j * 4 + 1) * 1024];
            float v2 = latb[(size_t)(j * 4 + 2) * 1024];
            float v3 = latb[(size_t)(j * 4 + 3) * 1024];
            uint32_t p0 = ((uint32_t)__bfloat16_as_ushort(__float2bfloat16(v1)) << 16)
                        |  (uint32_t)__bfloat16_as_ushort(__float2bfloat16(v0));
            uint32_t p1 = ((uint32_t)__bfloat16_as_ushort(__float2bfloat16(v3)) << 16)
                        |  (uint32_t)__bfloat16_as_ushort(__float2bfloat16(v2));
            arow[j * 2]     = p0;
            arow[j * 2 + 1] = p1;
        }
    }
    __syncthreads();                            // A staged; mbar init visible

    // Prologue: fetch halves 0 and 1.
    if (tid == 0) {
        asm volatile("mbarrier.arrive.expect_tx.shared.b64 _, [%0], %1;"
                     :: "r"(smb + MB_OFF), "r"((uint32_t)B_HALF) : "memory");
        bulk_cp(smb + B0_OFF, g_eb, B_HALF, smb + MB_OFF);
        asm volatile("mbarrier.arrive.expect_tx.shared.b64 _, [%0], %1;"
                     :: "r"(smb + MB_OFF + 16), "r"((uint32_t)B_HALF) : "memory");
        bulk_cp(smb + B1_OFF, g_eb + (size_t)KH * DD, B_HALF, smb + MB_OFF + 16);
    }

    uint32_t aAddr[2];
    #pragma unroll
    for (int mi = 0; mi < 2; mi++)
        aAddr[mi] = smb + A_OFF + (uint32_t)(((wm * 32 + mi * 16 + (lane & 15)) * ASTR
                                              + (lane >> 4) * 8) * 2);
    // B per-lane row params (row within 64-code half)
    const uint32_t hs = (lane >> 3) & 1;
    const uint32_t brow = (uint32_t)(wn * 16 + (lane & 7) + ((lane >> 4) & 1) * 8);
    const uint32_t brx  = brow & 7;
    const uint32_t browoff = brow * BROW;

    for (int i = 0; i < NH; i++) {
        const int kb = i * KH;
        const uint32_t boff = (i & 1) ? B1_OFF : B0_OFF;
        const uint32_t mbar = smb + MB_OFF + (i & 1) * 16;
        mbar_wait(mbar, (i >> 1) & 1);

        float acc[2][2][4];
        #pragma unroll
        for (int mi = 0; mi < 2; mi++)
            #pragma unroll
            for (int ni = 0; ni < 2; ni++)
                #pragma unroll
                for (int jj = 0; jj < 4; jj++) acc[mi][ni][jj] = 0.0f;

        const uint32_t bBase = smb + boff + browoff;
        #pragma unroll
        for (int ds = 0; ds < 16; ds++) {
            uint32_t a[2][4], bfr[2][2];
            #pragma unroll
            for (int mi = 0; mi < 2; mi++)
                ldsm4(a[mi][0], a[mi][1], a[mi][2], a[mi][3], aAddr[mi] + ds * 32);
            {
                uint32_t baddr = bBase + ((((uint32_t)(ds << 1) | hs) ^ brx) << 4);
                ldsm4(bfr[0][0], bfr[0][1], bfr[1][0], bfr[1][1], baddr);
            }
            #pragma unroll
            for (int mi = 0; mi < 2; mi++)
                #pragma unroll
                for (int ni = 0; ni < 2; ni++)
                    mma_bf16(acc[mi][ni][0], acc[mi][ni][1], acc[mi][ni][2], acc[mi][ni][3],
                             a[mi][0], a[mi][1], a[mi][2], a[mi][3],
                             bfr[ni][0], bfr[ni][1]);
        }

        // scores in place (enorm via L1-resident __ldg); per-row running min
        #pragma unroll
        for (int mi = 0; mi < 2; mi++) {
            float m0 = 3.4e38f, m1 = 3.4e38f;
            #pragma unroll
            for (int ni = 0; ni < 2; ni++) {
                int cl = wn * 16 + ni * 8 + 2 * tq;
                float e0 = __ldg(g_enorm + kb + cl);
                float e1 = __ldg(g_enorm + kb + cl + 1);
                acc[mi][ni][0] = e0 - 2.0f * acc[mi][ni][0];
                acc[mi][ni][1] = e1 - 2.0f * acc[mi][ni][1];
                acc[mi][ni][2] = e0 - 2.0f * acc[mi][ni][2];
                acc[mi][ni][3] = e1 - 2.0f * acc[mi][ni][3];
                m0 = fminf(m0, fminf(acc[mi][ni][0], acc[mi][ni][1]));
                m1 = fminf(m1, fminf(acc[mi][ni][2], acc[mi][ni][3]));
            }
            m0 = fminf(m0, __shfl_xor_sync(0xffffffffu, m0, 1));
            m0 = fminf(m0, __shfl_xor_sync(0xffffffffu, m0, 2));
            m1 = fminf(m1, __shfl_xor_sync(0xffffffffu, m1, 1));
            m1 = fminf(m1, __shfl_xor_sync(0xffffffffu, m1, 2));
            if (tq == 0) {
                atomicMin(&minval[wm * 32 + mi * 16 + g],     fenc(m0));
                atomicMin(&minval[wm * 32 + mi * 16 + g + 8], fenc(m1));
            }
        }
        __syncthreads();   // minval visible; ALL B reads of this buffer done

        // prefetch half i+2 into this buffer (overlaps with append below)
        if (tid == 0 && i + 2 < NH) {
            asm volatile("mbarrier.arrive.expect_tx.shared.b64 _, [%0], %1;"
                         :: "r"(mbar), "r"((uint32_t)B_HALF) : "memory");
            bulk_cp(smb + boff, g_eb + (size_t)(kb + 2 * KH) * DD, B_HALF, mbar);
        }

        // append candidates (conservative under pipelining: threshold only tightens)
        #pragma unroll
        for (int mi = 0; mi < 2; mi++) {
            int rl0 = wm * 32 + mi * 16 + g, rl1 = rl0 + 8;
            float t0 = fdec(minval[rl0]) + EPS;
            float t1 = fdec(minval[rl1]) + EPS;
            #pragma unroll
            for (int ni = 0; ni < 2; ni++) {
                int k0 = kb + wn * 16 + ni * 8 + 2 * tq;
                if (acc[mi][ni][0] <= t0) { int p = atomicAdd(&cnt[rl0], 1); if (p < CAP) cand[rl0 * CAP + p] = k0; }
                if (acc[mi][ni][1] <= t0) { int p = atomicAdd(&cnt[rl0], 1); if (p < CAP) cand[rl0 * CAP + p] = k0 + 1; }
                if (acc[mi][ni][2] <= t1) { int p = atomicAdd(&cnt[rl1], 1); if (p < CAP) cand[rl1 * CAP + p] = k0; }
                if (acc[mi][ni][3] <= t1) { int p = atomicAdd(&cnt[rl1], 1); if (p < CAP) cand[rl1 * CAP + p] = k0 + 1; }
            }
        }
    }
    __syncthreads();

    // ---- exact rescore: reload fp32 x over dead A/B tiles ----
    float* xrs = (float*)sm;                     // [64][XSTR] = 66560 B
    {
        const int hw = tid & 63, dg = tid >> 6;
        const float* latb = latent + ((size_t)b * DD + dg * 64) * 1024 + hw0 + hw;
        float* xrow = xrs + hw * XSTR + dg * 64;
        #pragma unroll 8
        for (int j = 0; j < 64; j++)
            xrow[j] = latb[(size_t)j * 1024];
    }
    __syncthreads();
    if (tid < MROWS) {
        const float4* xr = (const float4*)(xrs + tid * XSTR);
        float sum = 0.0f;
        #pragma unroll 8
        for (int i = 0; i < DD / 4; i++) {
            float4 v = xr[i];
            sum = __fadd_rn(sum, __fmul_rn(v.x, v.x));
            sum = __fadd_rn(sum, __fmul_rn(v.y, v.y));
            sum = __fadd_rn(sum, __fmul_rn(v.z, v.z));
            sum = __fadd_rn(sum, __fmul_rn(v.w, v.w));
        }
        xn_s[tid] = sum;
    }
    __syncthreads();
    {
        int r = tid >> 2, c0 = tid & 3;
        int cnr = cnt[r];
        float xn = xn_s[r];
        const float4* xp = (const float4*)(xrs + r * XSTR);
        float bs = 3.4e38f; int bi = 0x7fffffff;
        if (cnr <= CAP) {
            for (int cc = c0; cc < cnr; cc += 4) {
                int k = cand[r * CAP + cc];
                const float4* ep = (const float4*)(codebook + (size_t)k * DD);
                float a = 0.0f;
                #pragma unroll 8
                for (int i = 0; i < DD / 4; i++) {
                    float4 xv = xp[i], ev = ep[i];
                    a = fmaf(xv.x, ev.x, a); a = fmaf(xv.y, ev.y, a);
                    a = fmaf(xv.z, ev.z, a); a = fmaf(xv.w, ev.w, a);
                }
                float sc = __fsub_rn(__fadd_rn(xn, g_enorm[k]), __fmul_rn(2.0f, a));
                if (sc < bs || (sc == bs && k < bi)) { bs = sc; bi = k; }
            }
        } else {
            for (int k = c0; k < KK; k += 4) {   // backstop: exact scan
                const float4* ep = (const float4*)(codebook + (size_t)k * DD);
                float a = 0.0f;
                #pragma unroll 8
                for (int i = 0; i < DD / 4; i++) {
                    float4 xv = xp[i], ev = ep[i];
                    a = fmaf(xv.x, ev.x, a); a = fmaf(xv.y, ev.y, a);
                    a = fmaf(xv.z, ev.z, a); a = fmaf(xv.w, ev.w, a);
                }
                float sc = __fsub_rn(__fadd_rn(xn, g_enorm[k]), __fmul_rn(2.0f, a));
                if (sc < bs || (sc == bs && k < bi)) { bs = sc; bi = k; }
            }
        }
        bS[c0 * 64 + r] = bs;
        bK[c0 * 64 + r] = bi;
    }
    __syncthreads();
    if (tid < MROWS) {
        float bs = bS[tid]; int bi = bK[tid];
        #pragma unroll
        for (int cc = 1; cc < 4; cc++) {
            float s = bS[cc * 64 + tid]; int k = bK[cc * 64 + tid];
            if (s < bs || (s == bs && k < bi)) { bs = s; bi = k; }
        }
        idxs[tid] = bi;
    }
    __syncthreads();

    // ---- fused gather + output + loss ----
    {
        const int hw = tid & 63, dg = tid >> 6;
        const int kidx = idxs[hw];
        const float4* qrow  = (const float4*)(codebook + (size_t)kidx * DD + dg * 64);
        const float4* xrow4 = (const float4*)(xrs + hw * XSTR + dg * 64);
        float* outb = d_out + ((size_t)b * DD + dg * 64) * 1024 + hw0 + hw;
        float lsum = 0.0f;
        #pragma unroll
        for (int jq = 0; jq < 16; jq++) {
            float4 xv = xrow4[jq];
            float4 qv = __ldg(qrow + jq);
            float d0 = __fsub_rn(qv.x, xv.x);
            float d1 = __fsub_rn(qv.y, xv.y);
            float d2 = __fsub_rn(qv.z, xv.z);
            float d3 = __fsub_rn(qv.w, xv.w);
            outb[(size_t)(jq * 4 + 0) * 1024] = __fadd_rn(xv.x, d0);
            outb[(size_t)(jq * 4 + 1) * 1024] = __fadd_rn(xv.y, d1);
            outb[(size_t)(jq * 4 + 2) * 1024] = __fadd_rn(xv.z, d2);
            outb[(size_t)(jq * 4 + 3) * 1024] = __fadd_rn(xv.w, d3);
            lsum += d0 * d0 + d1 * d1 + d2 * d2 + d3 * d3;
        }
        float* red = (float*)cand;
        red[tid] = lsum;
        __syncthreads();
        #pragma unroll
        for (int s = 128; s > 0; s >>= 1) {
            if (tid < s) red[tid] += red[tid + s];
            __syncthreads();
        }
        if (tid == 0 && out_size > QSIZE)
            atomicAdd(d_out + QSIZE, 1.25f * red[0] * (1.0f / (float)QSIZE));
    }
}

extern "C" void kernel_launch(void* const* d_in, const int* in_sizes, int n_in,
                              void* d_out, int out_size) {
    const float* latent   = (const float*)d_in[0];
    const float* codebook = (const float*)d_in[1];
    float* out = (float*)d_out;

    cudaFuncSetAttribute(gemm_select_kernel,
                         cudaFuncAttributeMaxDynamicSharedMemorySize, SMEM_GEMM);

    prep_kernel<<<KK * 32 / 256, 256>>>(codebook, out, out_size);
    gemm_select_kernel<<<NVEC / MROWS, 256, SMEM_GEMM>>>(latent, codebook, out, out_size);
}

// round 16
// speedup vs baseline: 4.8890x; 1.1630x over previous
#include <cuda_runtime.h>
#include <cuda_bf16.h>
#include <cstdint>
#include <cstddef>

#define DD    256
#define KK    1024
#define NVEC  32768
#define QSIZE (32*256*32*32)

#define MROWS 64
#define KCH   128
#define NCH   8
#define ASTR  264          // A: bf16 elements per row (padded, R13-validated)
#define BROW  512          // B: bytes per code row (linear, swizzled content)
#define XSTR  260          // fp32 rescore tile stride
#define CAP   28
#define EPS   4e-3f        // validated: zero flips

__device__ float g_enorm[KK];
__device__ __align__(16) __nv_bfloat16 g_eb[KK * DD];   // PRE-SWIZZLED rows

// ---- smem layout (bytes); ~107 KB -> 2 CTAs/SM ----
#define A_OFF    0
#define A_B      (MROWS * ASTR * 2)          // 33792
#define B_OFF    A_B
#define B_B      (KCH * BROW)                // 65536
#define CTRL     (A_B + B_B)                 // 99328
#define MV_OFF   (CTRL)                      // 64 u32
#define CT_OFF   (MV_OFF + 256)              // 64 i32
#define XN_OFF   (CT_OFF + 256)              // 64 f32
#define IDX_OFF  (XN_OFF + 256)              // 64 i32
#define MB_OFF   (IDX_OFF + 256)             // mbarrier (16 B)
#define CAND_OFF (MB_OFF + 16)               // 64*CAP i32 = 7168
#define BS_OFF   (CAND_OFF + 64*CAP*4)       // 256 f32
#define BK_OFF   (BS_OFF + 1024)             // 256 i32
#define SMEM_GEMM (BK_OFF + 1024)            // 108576 B

__device__ __forceinline__ unsigned fenc(float f) {
    unsigned u = __float_as_uint(f);
    return (u & 0x80000000u) ? ~u : (u | 0x80000000u);
}
__device__ __forceinline__ float fdec(unsigned e) {
    return __uint_as_float((e & 0x80000000u) ? (e ^ 0x80000000u) : ~e);
}
__device__ __forceinline__ void bulk_cp(uint32_t dst, const void* src,
                                        uint32_t bytes, uint32_t mbar) {
    asm volatile(
        "cp.async.bulk.shared::cluster.global.mbarrier::complete_tx::bytes "
        "[%0], [%1], %2, [%3];"
        :: "r"(dst), "l"(src), "r"(bytes), "r"(mbar) : "memory");
}
__device__ __forceinline__ void mbar_wait(uint32_t mbar, unsigned parity) {
    asm volatile(
        "{\n\t.reg .pred P1;\n\t"
        "WL_%=:\n\t"
        "mbarrier.try_wait.parity.acquire.cta.shared::cta.b64 P1, [%0], %1, 0x989680;\n\t"
        "@P1 bra.uni WD_%=;\n\t"
        "bra.uni WL_%=;\n\t"
        "WD_%=:\n\t}"
        :: "r"(mbar), "r"(parity) : "memory");
}
__device__ __forceinline__ void ldsm4(uint32_t& r0, uint32_t& r1,
                                      uint32_t& r2, uint32_t& r3, uint32_t a) {
    asm volatile("ldmatrix.sync.aligned.m8n8.x4.shared.b16 {%0,%1,%2,%3}, [%4];"
                 : "=r"(r0), "=r"(r1), "=r"(r2), "=r"(r3) : "r"(a));
}
__device__ __forceinline__ void mma_bf16(float& c0, float& c1, float& c2, float& c3,
                                         uint32_t a0, uint32_t a1, uint32_t a2, uint32_t a3,
                                         uint32_t b0, uint32_t b1) {
    asm volatile("mma.sync.aligned.m16n8k16.row.col.f32.bf16.bf16.f32 "
                 "{%0,%1,%2,%3},{%4,%5,%6,%7},{%8,%9},{%0,%1,%2,%3};"
                 : "+f"(c0), "+f"(c1), "+f"(c2), "+f"(c3)
                 : "r"(a0), "r"(a1), "r"(a2), "r"(a3), "r"(b0), "r"(b1));
}

// ---------------------------------------------------------------------------
// prep: enorm + PRE-SWIZZLED bf16 codebook (chunk-XOR within 512B rows).
// ---------------------------------------------------------------------------
__global__ void __launch_bounds__(256)
prep_kernel(const float* __restrict__ codebook,
            float* __restrict__ d_out, int out_size) {
    int t = blockIdx.x * blockDim.x + threadIdx.x;
    int k = t >> 5, lane = t & 31;
    if (k < KK) {
        const float* p = codebook + (size_t)k * DD;
        const int sw = (k & 7) << 3;
        float s = 0.0f;
        #pragma unroll
        for (int j = 0; j < DD / 32; j++) {
            int d = lane + j * 32;
            float v = p[d];
            g_eb[(size_t)k * DD + (d ^ sw)] = __float2bfloat16(v);
            s = __fadd_rn(s, __fmul_rn(v, v));
        }
        #pragma unroll
        for (int o = 16; o; o >>= 1) s += __shfl_down_sync(0xffffffffu, s, o);
        if (lane == 0) g_enorm[k] = s;
    }
    if (t == 0 && out_size > QSIZE) d_out[QSIZE] = 0.0f;
}

// ---------------------------------------------------------------------------
// Fused GEMM (single B buffer, TMA for chunk c+1 hidden under epilogue of c)
// + select + exact rescore + gather/output + loss. 2 CTAs/SM.
// ---------------------------------------------------------------------------
__global__ void __launch_bounds__(256, 2)
gemm_select_kernel(const float* __restrict__ latent,
                   const float* __restrict__ codebook,
                   float* __restrict__ d_out, int out_size) {
    extern __shared__ __align__(1024) char sm[];
    const uint32_t smb = (uint32_t)__cvta_generic_to_shared(sm);
    __nv_bfloat16* As = (__nv_bfloat16*)(sm + A_OFF);
    unsigned* minval  = (unsigned*)(sm + MV_OFF);
    int*      cnt     = (int*)(sm + CT_OFF);
    float*    xn_s    = (float*)(sm + XN_OFF);
    int*      idxs    = (int*)(sm + IDX_OFF);
    int*      cand    = (int*)(sm + CAND_OFF);
    float*    bS      = (float*)(sm + BS_OFF);
    int*      bK      = (int*)(sm + BK_OFF);
    const uint32_t mbar = smb + MB_OFF;

    const int tid  = threadIdx.x;
    const int lane = tid & 31, wid = tid >> 5;
    const int wm   = wid >> 2, wn = wid & 3;     // 2 x 4 warp grid
    const int g    = lane >> 2, tq = lane & 3;
    const int n0   = blockIdx.x * MROWS;
    const int b    = n0 >> 10;
    const int hw0  = n0 & 1023;

    if (tid == 0)
        asm volatile("mbarrier.init.shared.b64 [%0], 1;" :: "r"(mbar) : "memory");
    if (tid < MROWS) { minval[tid] = 0xFFFFFFFFu; cnt[tid] = 0; }

    // Stage A from latent (R13-validated padded layout), coalesced over hw.
    {
        const int hw = tid & 63, dg = tid >> 6;
        const float* latb = latent + ((size_t)b * DD + dg * 64) * 1024 + hw0 + hw;
        uint32_t* arow = (uint32_t*)(As + hw * ASTR + dg * 64);
        #pragma unroll
        for (int j = 0; j < 16; j++) {
            float v0 = latb[(size_t)(j * 4 + 0) * 1024];
            float v1 = latb[(size_t)(j * 4 + 1) * 1024];
            float v2 = latb[(size_t)(j * 4 + 2) * 1024];
            float v3 = latb[(size_t)(j * 4 + 3) * 1024];
            uint32_t p0 = ((uint32_t)__bfloat16_as_ushort(__float2bfloat16(v1)) << 16)
                        |  (uint32_t)__bfloat16_as_ushort(__float2bfloat16(v0));
            uint32_t p1 = ((uint32_t)__bfloat16_as_ushort(__float2bfloat16(v3)) << 16)
                        |  (uint32_t)__bfloat16_as_ushort(__float2bfloat16(v2));
            arow[j * 2]     = p0;
            arow[j * 2 + 1] = p1;
        }
    }
    __syncthreads();                            // A staged; mbar init visible

    // Prologue: fetch chunk 0.
    if (tid == 0) {
        asm volatile("mbarrier.arrive.expect_tx.shared.b64 _, [%0], %1;"
                     :: "r"(mbar), "r"((uint32_t)B_B) : "memory");
        bulk_cp(smb + B_OFF, g_eb, B_B, mbar);
    }

    uint32_t aAddr[2], bAddr[2];
    #pragma unroll
    for (int mi = 0; mi < 2; mi++)
        aAddr[mi] = smb + A_OFF + (uint32_t)(((wm * 32 + mi * 16 + (lane & 15)) * ASTR
                                              + (lane >> 4) * 8) * 2);
    const uint32_t hs = (lane >> 3) & 1;
    uint32_t brx[2];
    #pragma unroll
    for (int nb = 0; nb < 2; nb++) {
        uint32_t r = wn * 32 + nb * 16 + (lane & 7) + ((lane >> 4) & 1) * 8;
        bAddr[nb] = smb + B_OFF + r * BROW;
        brx[nb] = r & 7;
    }

    for (int c = 0; c < NCH; c++) {
        const int kb = c * KCH;
        mbar_wait(mbar, c & 1);                  // chunk c data ready

        float acc[2][4][4];
        #pragma unroll
        for (int mi = 0; mi < 2; mi++)
            #pragma unroll
            for (int ni = 0; ni < 4; ni++)
                #pragma unroll
                for (int jj = 0; jj < 4; jj++) acc[mi][ni][jj] = 0.0f;

        #pragma unroll
        for (int ds = 0; ds < 16; ds++) {
            uint32_t a[2][4], bfr[4][2];
            #pragma unroll
            for (int mi = 0; mi < 2; mi++)
                ldsm4(a[mi][0], a[mi][1], a[mi][2], a[mi][3], aAddr[mi] + ds * 32);
            #pragma unroll
            for (int nb = 0; nb < 2; nb++) {
                uint32_t baddr = bAddr[nb] + ((((uint32_t)(ds << 1) | hs) ^ brx[nb]) << 4);
                ldsm4(bfr[2*nb][0], bfr[2*nb][1], bfr[2*nb+1][0], bfr[2*nb+1][1], baddr);
            }
            #pragma unroll
            for (int mi = 0; mi < 2; mi++)
                #pragma unroll
                for (int ni = 0; ni < 4; ni++)
                    mma_bf16(acc[mi][ni][0], acc[mi][ni][1], acc[mi][ni][2], acc[mi][ni][3],
                             a[mi][0], a[mi][1], a[mi][2], a[mi][3],
                             bfr[ni][0], bfr[ni][1]);
        }
        __syncthreads();                         // ALL B reads of chunk c done

        // issue TMA for chunk c+1 into the same buffer; hides under epilogue
        if (tid == 0 && c + 1 < NCH) {
            asm volatile("mbarrier.arrive.expect_tx.shared.b64 _, [%0], %1;"
                         :: "r"(mbar), "r"((uint32_t)B_B) : "memory");
            bulk_cp(smb + B_OFF, g_eb + (size_t)(kb + KCH) * DD, B_B, mbar);
        }

        // scores in place (enorm via L1-resident __ldg); per-row running min
        #pragma unroll
        for (int mi = 0; mi < 2; mi++) {
            float m0 = 3.4e38f, m1 = 3.4e38f;
            #pragma unroll
            for (int ni = 0; ni < 4; ni++) {
                int cl = wn * 32 + ni * 8 + 2 * tq;
                float e0 = __ldg(g_enorm + kb + cl);
                float e1 = __ldg(g_enorm + kb + cl + 1);
                acc[mi][ni][0] = e0 - 2.0f * acc[mi][ni][0];
                acc[mi][ni][1] = e1 - 2.0f * acc[mi][ni][1];
                acc[mi][ni][2] = e0 - 2.0f * acc[mi][ni][2];
                acc[mi][ni][3] = e1 - 2.0f * acc[mi][ni][3];
                m0 = fminf(m0, fminf(acc[mi][ni][0], acc[mi][ni][1]));
                m1 = fminf(m1, fminf(acc[mi][ni][2], acc[mi][ni][3]));
            }
            m0 = fminf(m0, __shfl_xor_sync(0xffffffffu, m0, 1));
            m0 = fminf(m0, __shfl_xor_sync(0xffffffffu, m0, 2));
            m1 = fminf(m1, __shfl_xor_sync(0xffffffffu, m1, 1));
            m1 = fminf(m1, __shfl_xor_sync(0xffffffffu, m1, 2));
            if (tq == 0) {
                atomicMin(&minval[wm * 32 + mi * 16 + g],     fenc(m0));
                atomicMin(&minval[wm * 32 + mi * 16 + g + 8], fenc(m1));
            }
        }
        __syncthreads();                         // minval visible

        // append candidates within EPS of running min
        #pragma unroll
        for (int mi = 0; mi < 2; mi++) {
            int rl0 = wm * 32 + mi * 16 + g, rl1 = rl0 + 8;
            float t0 = fdec(minval[rl0]) + EPS;
            float t1 = fdec(minval[rl1]) + EPS;
            #pragma unroll
            for (int ni = 0; ni < 4; ni++) {
                int k0 = kb + wn * 32 + ni * 8 + 2 * tq;
                if (acc[mi][ni][0] <= t0) { int p = atomicAdd(&cnt[rl0], 1); if (p < CAP) cand[rl0 * CAP + p] = k0; }
                if (acc[mi][ni][1] <= t0) { int p = atomicAdd(&cnt[rl0], 1); if (p < CAP) cand[rl0 * CAP + p] = k0 + 1; }
                if (acc[mi][ni][2] <= t1) { int p = atomicAdd(&cnt[rl1], 1); if (p < CAP) cand[rl1 * CAP + p] = k0; }
                if (acc[mi][ni][3] <= t1) { int p = atomicAdd(&cnt[rl1], 1); if (p < CAP) cand[rl1 * CAP + p] = k0 + 1; }
            }
        }
    }
    __syncthreads();

    // ---- exact rescore: reload fp32 x over dead A/B tiles ----
    float* xrs = (float*)sm;                     // [64][XSTR] = 66560 B
    {
        const int hw = tid & 63, dg = tid >> 6;
        const float* latb = latent + ((size_t)b * DD + dg * 64) * 1024 + hw0 + hw;
        float* xrow = xrs + hw * XSTR + dg * 64;
        #pragma unroll 8
        for (int j = 0; j < 64; j++)
            xrow[j] = latb[(size_t)j * 1024];
    }
    __syncthreads();
    if (tid < MROWS) {
        const float4* xr = (const float4*)(xrs + tid * XSTR);
        float sum = 0.0f;
        #pragma unroll 8
        for (int i = 0; i < DD / 4; i++) {
            float4 v = xr[i];
            sum = __fadd_rn(sum, __fmul_rn(v.x, v.x));
            sum = __fadd_rn(sum, __fmul_rn(v.y, v.y));
            sum = __fadd_rn(sum, __fmul_rn(v.z, v.z));
            sum = __fadd_rn(sum, __fmul_rn(v.w, v.w));
        }
        xn_s[tid] = sum;
    }
    __syncthreads();
    {
        int r = tid >> 2, c0 = tid & 3;
        int cnr = cnt[r];
        float xn = xn_s[r];
        const float4* xp = (const float4*)(xrs + r * XSTR);
        float bs = 3.4e38f; int bi = 0x7fffffff;
        if (cnr <= CAP) {
            for (int cc = c0; cc < cnr; cc += 4) {
                int k = cand[r * CAP + cc];
                const float4* ep = (const float4*)(codebook + (size_t)k * DD);
                float a = 0.0f;
                #pragma unroll 8
                for (int i = 0; i < DD / 4; i++) {
                    float4 xv = xp[i], ev = ep[i];
                    a = fmaf(xv.x, ev.x, a); a = fmaf(xv.y, ev.y, a);
                    a = fmaf(xv.z, ev.z, a); a = fmaf(xv.w, ev.w, a);
                }
                float sc = __fsub_rn(__fadd_rn(xn, g_enorm[k]), __fmul_rn(2.0f, a));
                if (sc < bs || (sc == bs && k < bi)) { bs = sc; bi = k; }
            }
        } else {
            for (int k = c0; k < KK; k += 4) {   // backstop: exact scan
                const float4* ep = (const float4*)(codebook + (size_t)k * DD);
                float a = 0.0f;
                #pragma unroll 8
                for (int i = 0; i < DD / 4; i++) {
                    float4 xv = xp[i], ev = ep[i];
                    a = fmaf(xv.x, ev.x, a); a = fmaf(xv.y, ev.y, a);
                    a = fmaf(xv.z, ev.z, a); a = fmaf(xv.w, ev.w, a);
                }
                float sc = __fsub_rn(__fadd_rn(xn, g_enorm[k]), __fmul_rn(2.0f, a));
                if (sc < bs || (sc == bs && k < bi)) { bs = sc; bi = k; }
            }
        }
        bS[c0 * 64 + r] = bs;
        bK[c0 * 64 + r] = bi;
    }
    __syncthreads();
    if (tid < MROWS) {
        float bs = bS[tid]; int bi = bK[tid];
        #pragma unroll
        for (int cc = 1; cc < 4; cc++) {
            float s = bS[cc * 64 + tid]; int k = bK[cc * 64 + tid];
            if (s < bs || (s == bs && k < bi)) { bs = s; bi = k; }
        }
        idxs[tid] = bi;
    }
    __syncthreads();

    // ---- fused gather + output + loss ----
    {
        const int hw = tid & 63, dg = tid >> 6;
        const int kidx = idxs[hw];
        const float4* qrow  = (const float4*)(codebook + (size_t)kidx * DD + dg * 64);
        const float4* xrow4 = (const float4*)(xrs + hw * XSTR + dg * 64);
        float* outb = d_out + ((size_t)b * DD + dg * 64) * 1024 + hw0 + hw;
        float lsum = 0.0f;
        #pragma unroll
        for (int jq = 0; jq < 16; jq++) {
            float4 xv = xrow4[jq];
            float4 qv = __ldg(qrow + jq);
            float d0 = __fsub_rn(qv.x, xv.x);
            float d1 = __fsub_rn(qv.y, xv.y);
            float d2 = __fsub_rn(qv.z, xv.z);
            float d3 = __fsub_rn(qv.w, xv.w);
            outb[(size_t)(jq * 4 + 0) * 1024] = __fadd_rn(xv.x, d0);
            outb[(size_t)(jq * 4 + 1) * 1024] = __fadd_rn(xv.y, d1);
            outb[(size_t)(jq * 4 + 2) * 1024] = __fadd_rn(xv.z, d2);
            outb[(size_t)(jq * 4 + 3) * 1024] = __fadd_rn(xv.w, d3);
            lsum += d0 * d0 + d1 * d1 + d2 * d2 + d3 * d3;
        }
        float* red = (float*)cand;
        red[tid] = lsum;
        __syncthreads();
        #pragma unroll
        for (int s = 128; s > 0; s >>= 1) {
            if (tid < s) red[tid] += red[tid + s];
            __syncthreads();
        }
        if (tid == 0 && out_size > QSIZE)
            atomicAdd(d_out + QSIZE, 1.25f * red[0] * (1.0f / (float)QSIZE));
    }
}

extern "C" void kernel_launch(void* const* d_in, const int* in_sizes, int n_in,
                              void* d_out, int out_size) {
    const float* latent   = (const float*)d_in[0];
    const float* codebook = (const float*)d_in[1];
    float* out = (float*)d_out;

    cudaFuncSetAttribute(gemm_select_kernel,
                         cudaFuncAttributeMaxDynamicSharedMemorySize, SMEM_GEMM);

    prep_kernel<<<KK * 32 / 256, 256>>>(codebook, out, out_size);
    gemm_select_kernel<<<NVEC / MROWS, 256, SMEM_GEMM>>>(latent, codebook, out, out_size);
}

// round 17
// speedup vs baseline: 4.9119x; 1.0047x over previous
#include <cuda_runtime.h>
#include <cuda_bf16.h>
#include <cstdint>
#include <cstddef>

#define DD    256
#define KK    1024
#define NVEC  32768
#define QSIZE (32*256*32*32)

#define MROWS 64
#define KCH   128
#define NCH   8
#define ASTR  264          // A: bf16 elements per row (padded)
#define BROW  512          // B: bytes per code row (linear, swizzled content)
#define XSTR  260          // fp32 rescore tile stride
#define CAP   40
#define EPS   4e-3f        // >= 2*delta_bf16; validated zero flips

__device__ float g_enorm[KK];
__device__ __align__(16) __nv_bfloat16 g_eb[KK * DD];   // PRE-SWIZZLED rows

// ---- smem layout (bytes); ~111 KB -> 2 CTAs/SM ----
#define A_OFF    0
#define A_B      (MROWS * ASTR * 2)          // 33792
#define B_OFF    A_B
#define B_B      (KCH * BROW)                // 65536
#define CTRL     (A_B + B_B)                 // 99328
#define MV_OFF   (CTRL)                      // 64 u32
#define CT_OFF   (MV_OFF + 256)              // 64 i32
#define XN_OFF   (CT_OFF + 256)              // 64 f32
#define IDX_OFF  (XN_OFF + 256)              // 64 i32
#define MB_OFF   (IDX_OFF + 256)             // mbarrier (16 B)
#define CAND_OFF (MB_OFF + 16)               // 64*CAP i32 = 10240
#define BS_OFF   (CAND_OFF + 64*CAP*4)       // 256 f32
#define BK_OFF   (BS_OFF + 1024)             // 256 i32
#define SMEM_GEMM (BK_OFF + 1024)            // 111648 B

__device__ __forceinline__ unsigned fenc(float f) {
    unsigned u = __float_as_uint(f);
    return (u & 0x80000000u) ? ~u : (u | 0x80000000u);
}
__device__ __forceinline__ float fdec(unsigned e) {
    return __uint_as_float((e & 0x80000000u) ? (e ^ 0x80000000u) : ~e);
}
__device__ __forceinline__ void bulk_cp(uint32_t dst, const void* src,
                                        uint32_t bytes, uint32_t mbar) {
    asm volatile(
        "cp.async.bulk.shared::cluster.global.mbarrier::complete_tx::bytes "
        "[%0], [%1], %2, [%3];"
        :: "r"(dst), "l"(src), "r"(bytes), "r"(mbar) : "memory");
}
__device__ __forceinline__ void mbar_wait(uint32_t mbar, unsigned parity) {
    asm volatile(
        "{\n\t.reg .pred P1;\n\t"
        "WL_%=:\n\t"
        "mbarrier.try_wait.parity.acquire.cta.shared::cta.b64 P1, [%0], %1, 0x989680;\n\t"
        "@P1 bra.uni WD_%=;\n\t"
        "bra.uni WL_%=;\n\t"
        "WD_%=:\n\t}"
        :: "r"(mbar), "r"(parity) : "memory");
}
__device__ __forceinline__ void ldsm4(uint32_t& r0, uint32_t& r1,
                                      uint32_t& r2, uint32_t& r3, uint32_t a) {
    asm volatile("ldmatrix.sync.aligned.m8n8.x4.shared.b16 {%0,%1,%2,%3}, [%4];"
                 : "=r"(r0), "=r"(r1), "=r"(r2), "=r"(r3) : "r"(a));
}
__device__ __forceinline__ void mma_bf16(float& c0, float& c1, float& c2, float& c3,
                                         uint32_t a0, uint32_t a1, uint32_t a2, uint32_t a3,
                                         uint32_t b0, uint32_t b1) {
    asm volatile("mma.sync.aligned.m16n8k16.row.col.f32.bf16.bf16.f32 "
                 "{%0,%1,%2,%3},{%4,%5,%6,%7},{%8,%9},{%0,%1,%2,%3};"
                 : "+f"(c0), "+f"(c1), "+f"(c2), "+f"(c3)
                 : "r"(a0), "r"(a1), "r"(a2), "r"(a3), "r"(b0), "r"(b1));
}

// ---------------------------------------------------------------------------
// prep: enorm + PRE-SWIZZLED bf16 codebook (chunk-XOR within 512B rows).
// ---------------------------------------------------------------------------
__global__ void __launch_bounds__(256)
prep_kernel(const float* __restrict__ codebook,
            float* __restrict__ d_out, int out_size) {
    int t = blockIdx.x * blockDim.x + threadIdx.x;
    int k = t >> 5, lane = t & 31;
    if (k < KK) {
        const float* p = codebook + (size_t)k * DD;
        const int sw = (k & 7) << 3;
        float s = 0.0f;
        #pragma unroll
        for (int j = 0; j < DD / 32; j++) {
            int d = lane + j * 32;
            float v = p[d];
            g_eb[(size_t)k * DD + (d ^ sw)] = __float2bfloat16(v);
            s = __fadd_rn(s, __fmul_rn(v, v));
        }
        #pragma unroll
        for (int o = 16; o; o >>= 1) s += __shfl_down_sync(0xffffffffu, s, o);
        if (lane == 0) g_enorm[k] = s;
    }
    if (t == 0 && out_size > QSIZE) d_out[QSIZE] = 0.0f;
}

// ---------------------------------------------------------------------------
// Fused GEMM + select (1 barrier/chunk; stale-threshold appends, chunk 0
// barriered to clear the init sentinel) + exact rescore + gather + loss.
// ---------------------------------------------------------------------------
__global__ void __launch_bounds__(256, 2)
gemm_select_kernel(const float* __restrict__ latent,
                   const float* __restrict__ codebook,
                   float* __restrict__ d_out, int out_size) {
    extern __shared__ __align__(1024) char sm[];
    const uint32_t smb = (uint32_t)__cvta_generic_to_shared(sm);
    __nv_bfloat16* As = (__nv_bfloat16*)(sm + A_OFF);
    unsigned* minval  = (unsigned*)(sm + MV_OFF);
    int*      cnt     = (int*)(sm + CT_OFF);
    float*    xn_s    = (float*)(sm + XN_OFF);
    int*      idxs    = (int*)(sm + IDX_OFF);
    int*      cand    = (int*)(sm + CAND_OFF);
    float*    bS      = (float*)(sm + BS_OFF);
    int*      bK      = (int*)(sm + BK_OFF);
    const uint32_t mbar = smb + MB_OFF;

    const int tid  = threadIdx.x;
    const int lane = tid & 31, wid = tid >> 5;
    const int wm   = wid >> 2, wn = wid & 3;     // 2 x 4 warp grid
    const int g    = lane >> 2, tq = lane & 3;
    const int n0   = blockIdx.x * MROWS;
    const int b    = n0 >> 10;
    const int hw0  = n0 & 1023;

    if (tid == 0)
        asm volatile("mbarrier.init.shared.b64 [%0], 1;" :: "r"(mbar) : "memory");
    if (tid < MROWS) { minval[tid] = 0xFFFFFFFFu; cnt[tid] = 0; }

    // Stage A from latent (padded layout), coalesced over hw.
    {
        const int hw = tid & 63, dg = tid >> 6;
        const float* latb = latent + ((size_t)b * DD + dg * 64) * 1024 + hw0 + hw;
        uint32_t* arow = (uint32_t*)(As + hw * ASTR + dg * 64);
        #pragma unroll
        for (int j = 0; j < 16; j++) {
            float v0 = latb[(size_t)(j * 4 + 0) * 1024];
            float v1 = latb[(size_t)(j * 4 + 1) * 1024];
            float v2 = latb[(size_t)(j * 4 + 2) * 1024];
            float v3 = latb[(size_t)(j * 4 + 3) * 1024];
            uint32_t p0 = ((uint32_t)__bfloat16_as_ushort(__float2bfloat16(v1)) << 16)
                        |  (uint32_t)__bfloat16_as_ushort(__float2bfloat16(v0));
            uint32_t p1 = ((uint32_t)__bfloat16_as_ushort(__float2bfloat16(v3)) << 16)
                        |  (uint32_t)__bfloat16_as_ushort(__float2bfloat16(v2));
            arow[j * 2]     = p0;
            arow[j * 2 + 1] = p1;
        }
    }
    __syncthreads();                            // A staged; mbar init visible

    // Prologue: fetch chunk 0.
    if (tid == 0) {
        asm volatile("mbarrier.arrive.expect_tx.shared.b64 _, [%0], %1;"
                     :: "r"(mbar), "r"((uint32_t)B_B) : "memory");
        bulk_cp(smb + B_OFF, g_eb, B_B, mbar);
    }

    uint32_t aAddr[2], bAddr[2];
    #pragma unroll
    for (int mi = 0; mi < 2; mi++)
        aAddr[mi] = smb + A_OFF + (uint32_t)(((wm * 32 + mi * 16 + (lane & 15)) * ASTR
                                              + (lane >> 4) * 8) * 2);
    const uint32_t hs = (lane >> 3) & 1;
    uint32_t brx[2];
    #pragma unroll
    for (int nb = 0; nb < 2; nb++) {
        uint32_t r = wn * 32 + nb * 16 + (lane & 7) + ((lane >> 4) & 1) * 8;
        bAddr[nb] = smb + B_OFF + r * BROW;
        brx[nb] = r & 7;
    }

    for (int c = 0; c < NCH; c++) {
        const int kb = c * KCH;
        mbar_wait(mbar, c & 1);                  // chunk c data ready

        float acc[2][4][4];
        #pragma unroll
        for (int mi = 0; mi < 2; mi++)
            #pragma unroll
            for (int ni = 0; ni < 4; ni++)
                #pragma unroll
                for (int jj = 0; jj < 4; jj++) acc[mi][ni][jj] = 0.0f;

        #pragma unroll
        for (int ds = 0; ds < 16; ds++) {
            uint32_t a[2][4], bfr[4][2];
            #pragma unroll
            for (int mi = 0; mi < 2; mi++)
                ldsm4(a[mi][0], a[mi][1], a[mi][2], a[mi][3], aAddr[mi] + ds * 32);
            #pragma unroll
            for (int nb = 0; nb < 2; nb++) {
                uint32_t baddr = bAddr[nb] + ((((uint32_t)(ds << 1) | hs) ^ brx[nb]) << 4);
                ldsm4(bfr[2*nb][0], bfr[2*nb][1], bfr[2*nb+1][0], bfr[2*nb+1][1], baddr);
            }
            #pragma unroll
            for (int mi = 0; mi < 2; mi++)
                #pragma unroll
                for (int ni = 0; ni < 4; ni++)
                    mma_bf16(acc[mi][ni][0], acc[mi][ni][1], acc[mi][ni][2], acc[mi][ni][3],
                             a[mi][0], a[mi][1], a[mi][2], a[mi][3],
                             bfr[ni][0], bfr[ni][1]);
        }
        __syncthreads();                         // ALL B reads of chunk c done

        // TMA for chunk c+1 (same buffer); hides under min/append phases
        if (tid == 0 && c + 1 < NCH) {
            asm volatile("mbarrier.arrive.expect_tx.shared.b64 _, [%0], %1;"
                         :: "r"(mbar), "r"((uint32_t)B_B) : "memory");
            bulk_cp(smb + B_OFF, g_eb + (size_t)(kb + KCH) * DD, B_B, mbar);
        }

        // scores in place; per-row running min via atomicMin
        #pragma unroll
        for (int mi = 0; mi < 2; mi++) {
            float m0 = 3.4e38f, m1 = 3.4e38f;
            #pragma unroll
            for (int ni = 0; ni < 4; ni++) {
                int cl = wn * 32 + ni * 8 + 2 * tq;
                float e0 = __ldg(g_enorm + kb + cl);
                float e1 = __ldg(g_enorm + kb + cl + 1);
                acc[mi][ni][0] = e0 - 2.0f * acc[mi][ni][0];
                acc[mi][ni][1] = e1 - 2.0f * acc[mi][ni][1];
                acc[mi][ni][2] = e0 - 2.0f * acc[mi][ni][2];
                acc[mi][ni][3] = e1 - 2.0f * acc[mi][ni][3];
                m0 = fminf(m0, fminf(acc[mi][ni][0], acc[mi][ni][1]));
                m1 = fminf(m1, fminf(acc[mi][ni][2], acc[mi][ni][3]));
            }
            m0 = fminf(m0, __shfl_xor_sync(0xffffffffu, m0, 1));
            m0 = fminf(m0, __shfl_xor_sync(0xffffffffu, m0, 2));
            m1 = fminf(m1, __shfl_xor_sync(0xffffffffu, m1, 1));
            m1 = fminf(m1, __shfl_xor_sync(0xffffffffu, m1, 2));
            if (tq == 0) {
                atomicMin(&minval[wm * 32 + mi * 16 + g],     fenc(m0));
                atomicMin(&minval[wm * 32 + mi * 16 + g + 8], fenc(m1));
            }
        }
        // Chunk 0 only: ensure every row's minval holds a genuine value
        // (clears the NaN-decoding init sentinel). Later chunks append with
        // possibly-stale minval — provably conservative since EPS >= 2*delta.
        if (c == 0) __syncthreads();

        #pragma unroll
        for (int mi = 0; mi < 2; mi++) {
            int rl0 = wm * 32 + mi * 16 + g, rl1 = rl0 + 8;
            float t0 = fdec(minval[rl0]) + EPS;
            float t1 = fdec(minval[rl1]) + EPS;
            #pragma unroll
            for (int ni = 0; ni < 4; ni++) {
                int k0 = kb + wn * 32 + ni * 8 + 2 * tq;
                if (acc[mi][ni][0] <= t0) { int p = atomicAdd(&cnt[rl0], 1); if (p < CAP) cand[rl0 * CAP + p] = k0; }
                if (acc[mi][ni][1] <= t0) { int p = atomicAdd(&cnt[rl0], 1); if (p < CAP) cand[rl0 * CAP + p] = k0 + 1; }
                if (acc[mi][ni][2] <= t1) { int p = atomicAdd(&cnt[rl1], 1); if (p < CAP) cand[rl1 * CAP + p] = k0; }
                if (acc[mi][ni][3] <= t1) { int p = atomicAdd(&cnt[rl1], 1); if (p < CAP) cand[rl1 * CAP + p] = k0 + 1; }
            }
        }
    }
    __syncthreads();

    // ---- exact rescore: reload fp32 x over dead A/B tiles ----
    float* xrs = (float*)sm;                     // [64][XSTR] = 66560 B
    {
        const int hw = tid & 63, dg = tid >> 6;
        const float* latb = latent + ((size_t)b * DD + dg * 64) * 1024 + hw0 + hw;
        float* xrow = xrs + hw * XSTR + dg * 64;
        #pragma unroll 8
        for (int j = 0; j < 64; j++)
            xrow[j] = latb[(size_t)j * 1024];
    }
    __syncthreads();
    if (tid < MROWS) {
        const float4* xr = (const float4*)(xrs + tid * XSTR);
        float sum = 0.0f;
        #pragma unroll 8
        for (int i = 0; i < DD / 4; i++) {
            float4 v = xr[i];
            sum = __fadd_rn(sum, __fmul_rn(v.x, v.x));
            sum = __fadd_rn(sum, __fmul_rn(v.y, v.y));
            sum = __fadd_rn(sum, __fmul_rn(v.z, v.z));
            sum = __fadd_rn(sum, __fmul_rn(v.w, v.w));
        }
        xn_s[tid] = sum;
    }
    __syncthreads();
    {
        int r = tid >> 2, c0 = tid & 3;
        int cnr = cnt[r];
        float xn = xn_s[r];
        const float4* xp = (const float4*)(xrs + r * XSTR);
        float bs = 3.4e38f; int bi = 0x7fffffff;
        if (cnr <= CAP) {
            for (int cc = c0; cc < cnr; cc += 4) {
                int k = cand[r * CAP + cc];
                const float4* ep = (const float4*)(codebook + (size_t)k * DD);
                float a = 0.0f;
                #pragma unroll 8
                for (int i = 0; i < DD / 4; i++) {
                    float4 xv = xp[i], ev = ep[i];
                    a = fmaf(xv.x, ev.x, a); a = fmaf(xv.y, ev.y, a);
                    a = fmaf(xv.z, ev.z, a); a = fmaf(xv.w, ev.w, a);
                }
                float sc = __fsub_rn(__fadd_rn(xn, g_enorm[k]), __fmul_rn(2.0f, a));
                if (sc < bs || (sc == bs && k < bi)) { bs = sc; bi = k; }
            }
        } else {
            for (int k = c0; k < KK; k += 4) {   // backstop: exact scan
                const float4* ep = (const float4*)(codebook + (size_t)k * DD);
                float a = 0.0f;
                #pragma unroll 8
                for (int i = 0; i < DD / 4; i++) {
                    float4 xv = xp[i], ev = ep[i];
                    a = fmaf(xv.x, ev.x, a); a = fmaf(xv.y, ev.y, a);
                    a = fmaf(xv.z, ev.z, a); a = fmaf(xv.w, ev.w, a);
                }
                float sc = __fsub_rn(__fadd_rn(xn, g_enorm[k]), __fmul_rn(2.0f, a));
                if (sc < bs || (sc == bs && k < bi)) { bs = sc; bi = k; }
            }
        }
        bS[c0 * 64 + r] = bs;
        bK[c0 * 64 + r] = bi;
    }
    __syncthreads();
    if (tid < MROWS) {
        float bs = bS[tid]; int bi = bK[tid];
        #pragma unroll
        for (int cc = 1; cc < 4; cc++) {
            float s = bS[cc * 64 + tid]; int k = bK[cc * 64 + tid];
            if (s < bs || (s == bs && k < bi)) { bs = s; bi = k; }
        }
        idxs[tid] = bi;
    }
    __syncthreads();

    // ---- fused gather + output + loss ----
    {
        const int hw = tid & 63, dg = tid >> 6;
        const int kidx = idxs[hw];
        const float4* qrow  = (const float4*)(codebook + (size_t)kidx * DD + dg * 64);
        const float4* xrow4 = (const float4*)(xrs + hw * XSTR + dg * 64);
        float* outb = d_out + ((size_t)b * DD + dg * 64) * 1024 + hw0 + hw;
        float lsum = 0.0f;
        #pragma unroll
        for (int jq = 0; jq < 16; jq++) {
            float4 xv = xrow4[jq];
            float4 qv = __ldg(qrow + jq);
            float d0 = __fsub_rn(qv.x, xv.x);
            float d1 = __fsub_rn(qv.y, xv.y);
            float d2 = __fsub_rn(qv.z, xv.z);
            float d3 = __fsub_rn(qv.w, xv.w);
            outb[(size_t)(jq * 4 + 0) * 1024] = __fadd_rn(xv.x, d0);
            outb[(size_t)(jq * 4 + 1) * 1024] = __fadd_rn(xv.y, d1);
            outb[(size_t)(jq * 4 + 2) * 1024] = __fadd_rn(xv.z, d2);
            outb[(size_t)(jq * 4 + 3) * 1024] = __fadd_rn(xv.w, d3);
            lsum += d0 * d0 + d1 * d1 + d2 * d2 + d3 * d3;
        }
        float* red = (float*)cand;
        red[tid] = lsum;
        __syncthreads();
        #pragma unroll
        for (int s = 128; s > 0; s >>= 1) {
            if (tid < s) red[tid] += red[tid + s];
            __syncthreads();
        }
        if (tid == 0 && out_size > QSIZE)
            atomicAdd(d_out + QSIZE, 1.25f * red[0] * (1.0f / (float)QSIZE));
    }
}

extern "C" void kernel_launch(void* const* d_in, const int* in_sizes, int n_in,
                              void* d_out, int out_size) {
    const float* latent   = (const float*)d_in[0];
    const float* codebook = (const float*)d_in[1];
    float* out = (float*)d_out;

    cudaFuncSetAttribute(gemm_select_kernel,
                         cudaFuncAttributeMaxDynamicSharedMemorySize, SMEM_GEMM);

    prep_kernel<<<KK * 32 / 256, 256>>>(codebook, out, out_size);
    gemm_select_kernel<<<NVEC / MROWS, 256, SMEM_GEMM>>>(latent, codebook, out, out_size);
}